// round 1
// baseline (speedup 1.0000x reference)
#include <cuda_runtime.h>
#include <math.h>

#define NB     4
#define NQ     1024
#define DIM    256
#define NHEADS 8
#define NPTS   4
#define GH     200
#define GW     200
#define NHW    (GH*GW)       // 40000
#define NROWS  (NB*NQ)       // 4096

// Scratch (static __device__ arrays: allocation-free per harness rules)
__device__ float g_query[NROWS * DIM];
__device__ float g_off  [NROWS * 64];
__device__ float g_attn [NROWS * 32];
__device__ float g_value[(size_t)NB * NHW * DIM];   // ~164 MB
__device__ float g_samp [NROWS * DIM];
__device__ float g_msda [NROWS * DIM];

// ---------------------------------------------------------------------------
// GEMM: C[M x 256] = A @ W + bias (+ res). N fixed at 256.
// COLA=true : A stored [K][M] (k-major, lda = row stride in elements) -> value GEMM
// COLA=false: A stored [M][K] row-major
// 128x128 tile, BK=16, 256 threads, 8x8 per-thread microtile split 2x2 (float4 LDS)
// ---------------------------------------------------------------------------
template<bool COLA>
__global__ __launch_bounds__(256)
void gemm256(const float* __restrict__ A, const float* __restrict__ W,
             const float* __restrict__ bias, const float* __restrict__ res,
             float* __restrict__ C,
             int M, int K, int lda,
             long long strideA, long long strideC)
{
    __shared__ __align__(16) float As[16][128];
    __shared__ __align__(16) float Bs[16][128];

    const int tid = threadIdx.x;
    const int tx = tid & 15, ty = tid >> 4;
    const int n0 = blockIdx.x * 128;
    const int m0 = blockIdx.y * 128;
    A += blockIdx.z * strideA;
    C += blockIdx.z * strideC;

    float acc[8][8];
#pragma unroll
    for (int i = 0; i < 8; i++)
#pragma unroll
        for (int j = 0; j < 8; j++) acc[i][j] = 0.f;

    for (int k0 = 0; k0 < K; k0 += 16) {
        if (COLA) {
            // A[k][m], contiguous in m -> direct coalesced float4 loads
            const int kr = tid >> 4;          // 0..15
            const int mq = (tid & 15) * 8;    // 0..120
            const float* src = A + (size_t)(k0 + kr) * lda + m0 + mq;
            if (m0 + mq < M) {
                *(float4*)&As[kr][mq]     = *(const float4*)(src);
                *(float4*)&As[kr][mq + 4] = *(const float4*)(src + 4);
            } else {
                float4 z = make_float4(0.f, 0.f, 0.f, 0.f);
                *(float4*)&As[kr][mq]     = z;
                *(float4*)&As[kr][mq + 4] = z;
            }
        } else {
            // A[m][k] row-major: float4 along k, transpose into As[k][m]
            const int mr = tid >> 2;          // 0..63
            const int kq = (tid & 3) * 4;     // 0,4,8,12
#pragma unroll
            for (int r = 0; r < 2; r++) {
                const int m = mr + 64 * r;
                float4 v;
                if (m0 + m < M) v = *(const float4*)(A + (size_t)(m0 + m) * lda + k0 + kq);
                else            v = make_float4(0.f, 0.f, 0.f, 0.f);
                As[kq + 0][m] = v.x; As[kq + 1][m] = v.y;
                As[kq + 2][m] = v.z; As[kq + 3][m] = v.w;
            }
        }
        {
            const int kr = tid >> 4;
            const int nq = (tid & 15) * 8;
            const float* src = W + (size_t)(k0 + kr) * 256 + n0 + nq;
            *(float4*)&Bs[kr][nq]     = *(const float4*)(src);
            *(float4*)&Bs[kr][nq + 4] = *(const float4*)(src + 4);
        }
        __syncthreads();

#pragma unroll
        for (int k = 0; k < 16; k++) {
            float a[8], b[8];
            *(float4*)&a[0] = *(const float4*)&As[k][ty * 4];
            *(float4*)&a[4] = *(const float4*)&As[k][64 + ty * 4];
            *(float4*)&b[0] = *(const float4*)&Bs[k][tx * 4];
            *(float4*)&b[4] = *(const float4*)&Bs[k][64 + tx * 4];
#pragma unroll
            for (int i = 0; i < 8; i++)
#pragma unroll
                for (int j = 0; j < 8; j++)
                    acc[i][j] = fmaf(a[i], b[j], acc[i][j]);
        }
        __syncthreads();
    }

#pragma unroll
    for (int i = 0; i < 8; i++) {
        const int m = m0 + (i < 4 ? ty * 4 + i : 64 + ty * 4 + (i - 4));
        if (m >= M) continue;
#pragma unroll
        for (int j = 0; j < 8; j++) {
            const int n = n0 + (j < 4 ? tx * 4 + j : 64 + tx * 4 + (j - 4));
            float v = acc[i][j] + bias[n];
            if (res) v += res[(size_t)m * 256 + n];
            C[(size_t)m * 256 + n] = v;
        }
    }
}

// ---------------------------------------------------------------------------
// Offsets (64) + attn logits (32) + per-head softmax, one block per query row
// ---------------------------------------------------------------------------
__global__ __launch_bounds__(128)
void offattn_kernel(const float* __restrict__ q,
                    const float* __restrict__ Woff, const float* __restrict__ boff,
                    const float* __restrict__ Wattn, const float* __restrict__ battn,
                    float* __restrict__ off, float* __restrict__ attn)
{
    const int row = blockIdx.x;
    __shared__ float qs[256];
    __shared__ float lg[32];
    const int t = threadIdx.x;
    qs[t]       = q[(size_t)row * 256 + t];
    qs[t + 128] = q[(size_t)row * 256 + 128 + t];
    __syncthreads();

    if (t < 64) {
        float s = boff[t];
#pragma unroll 8
        for (int k = 0; k < 256; k++) s = fmaf(qs[k], Woff[k * 64 + t], s);
        off[(size_t)row * 64 + t] = s;
    } else if (t < 96) {
        const int j = t - 64;
        float s = battn[j];
#pragma unroll 8
        for (int k = 0; k < 256; k++) s = fmaf(qs[k], Wattn[k * 32 + j], s);
        lg[j] = s;
    }
    __syncthreads();

    if (t < 8) {
        float l0 = lg[t*4], l1 = lg[t*4+1], l2 = lg[t*4+2], l3 = lg[t*4+3];
        float m = fmaxf(fmaxf(l0, l1), fmaxf(l2, l3));
        float e0 = expf(l0 - m), e1 = expf(l1 - m), e2 = expf(l2 - m), e3 = expf(l3 - m);
        float inv = 1.f / (e0 + e1 + e2 + e3);
        attn[(size_t)row * 32 + t*4 + 0] = e0 * inv;
        attn[(size_t)row * 32 + t*4 + 1] = e1 * inv;
        attn[(size_t)row * 32 + t*4 + 2] = e2 * inv;
        attn[(size_t)row * 32 + t*4 + 3] = e3 * inv;
    }
}

// ---------------------------------------------------------------------------
// Bezier ref-center + bilinear sampling + attn-weighted sum.
// One block per (b,n); 8 warps = 8 heads; 32 lanes = HD channels (coalesced).
// ---------------------------------------------------------------------------
__global__ __launch_bounds__(256)
void sample_kernel(const float* __restrict__ ctrl, const float* __restrict__ pcr,
                   const float* __restrict__ value, const float* __restrict__ off,
                   const float* __restrict__ attn, float* __restrict__ samp)
{
    const int row = blockIdx.x;      // b*1024 + n
    const int b = row >> 10;
    __shared__ float rc[2];
    const int t = threadIdx.x;

    if (t == 0) {
        const float lox = pcr[0], loy = pcr[1];
        const float spx = pcr[3] - pcr[0], spy = pcr[4] - pcr[1];
        const float* cp = ctrl + (size_t)row * 8;
        const float c0x = cp[0], c0y = cp[1], c1x = cp[2], c1y = cp[3];
        const float c2x = cp[4], c2y = cp[5], c3x = cp[6], c3y = cp[7];
        float sx = 0.f, sy = 0.f;
#pragma unroll
        for (int k = 0; k < 10; k++) {
            const float tt = (float)k / 9.0f;
            const float u = 1.0f - tt;
            const float w0 = u*u*u, w1 = 3.f*u*u*tt, w2 = 3.f*u*tt*tt, w3 = tt*tt*tt;
            const float dx = w0*c0x + w1*c1x + w2*c2x + w3*c3x;
            const float dy = w0*c0y + w1*c1y + w2*c2y + w3*c3y;
            sx += fminf(fmaxf((dx - lox) / spx, 0.01f), 0.99f);
            sy += fminf(fmaxf((dy - loy) / spy, 0.01f), 0.99f);
        }
        rc[0] = sx * 0.1f;
        rc[1] = sy * 0.1f;
    }
    __syncthreads();

    const int h = t >> 5, lane = t & 31;
    const float* vb = value + ((size_t)b * NHW) * 256 + h * 32 + lane;
    const float rcx = rc[0], rcy = rc[1];
    float acc = 0.f;

#pragma unroll
    for (int p = 0; p < 4; p++) {
        const float ox = off[(size_t)row * 64 + h * 8 + p * 2 + 0];
        const float oy = off[(size_t)row * 64 + h * 8 + p * 2 + 1];
        const float lx = rcx + ox / (float)GW;
        const float ly = rcy + oy / (float)GH;
        const float x = lx * (float)GW - 0.5f;
        const float y = ly * (float)GH - 0.5f;
        const float fx = floorf(x), fy = floorf(y);
        const int x0 = (int)fx, y0 = (int)fy;
        const int x1 = x0 + 1,  y1 = y0 + 1;
        const float wx = x - fx, wy = y - fy;
        const float aw = attn[(size_t)row * 32 + h * 4 + p];
        const float w00 = (1.f - wx) * (1.f - wy) * aw;
        const float w01 = wx * (1.f - wy) * aw;
        const float w10 = (1.f - wx) * wy * aw;
        const float w11 = wx * wy * aw;
        const bool vx0 = (x0 >= 0) & (x0 < GW), vx1 = (x1 >= 0) & (x1 < GW);
        const bool vy0 = (y0 >= 0) & (y0 < GH), vy1 = (y1 >= 0) & (y1 < GH);
        if (vy0 & vx0) acc = fmaf(w00, vb[(size_t)(y0 * GW + x0) * 256], acc);
        if (vy0 & vx1) acc = fmaf(w01, vb[(size_t)(y0 * GW + x1) * 256], acc);
        if (vy1 & vx0) acc = fmaf(w10, vb[(size_t)(y1 * GW + x0) * 256], acc);
        if (vy1 & vx1) acc = fmaf(w11, vb[(size_t)(y1 * GW + x1) * 256], acc);
    }
    samp[(size_t)row * 256 + h * 32 + lane] = acc;
}

// ---------------------------------------------------------------------------
extern "C" void kernel_launch(void* const* d_in, const int* in_sizes, int n_in,
                              void* d_out, int out_size)
{
    const float* query_embed = (const float*)d_in[0];
    const float* ctrl        = (const float*)d_in[1];
    const float* bev         = (const float*)d_in[2];
    /* d_in[3] spatial_shapes unused */
    const float* pc_range    = (const float*)d_in[4];
    const float* W_q   = (const float*)d_in[5];
    const float* b_q   = (const float*)d_in[6];
    const float* W_val = (const float*)d_in[7];
    const float* b_val = (const float*)d_in[8];
    const float* W_off = (const float*)d_in[9];
    const float* b_off = (const float*)d_in[10];
    const float* W_attn = (const float*)d_in[11];
    const float* b_attn = (const float*)d_in[12];
    const float* W_do  = (const float*)d_in[13];
    const float* b_do  = (const float*)d_in[14];
    const float* W_out = (const float*)d_in[15];
    const float* b_out = (const float*)d_in[16];
    float* out = (float*)d_out;

    float *pq, *pv, *po, *pa, *ps, *pm;
    cudaGetSymbolAddress((void**)&pq, g_query);
    cudaGetSymbolAddress((void**)&pv, g_value);
    cudaGetSymbolAddress((void**)&po, g_off);
    cudaGetSymbolAddress((void**)&pa, g_attn);
    cudaGetSymbolAddress((void**)&ps, g_samp);
    cudaGetSymbolAddress((void**)&pm, g_msda);

    // 1) query = query_embed @ W_q + b_q
    gemm256<false><<<dim3(2, (NROWS + 127) / 128, 1), 256>>>(
        query_embed, W_q, b_q, nullptr, pq, NROWS, DIM, DIM, 0, 0);

    // 2) offsets / attn / softmax
    offattn_kernel<<<NROWS, 128>>>(pq, W_off, b_off, W_attn, b_attn, po, pa);

    // 3) value = bev^T @ W_val + b_val   (per batch; A is k-major with lda=NHW)
    gemm256<true><<<dim3(2, (NHW + 127) / 128, NB), 256>>>(
        bev, W_val, b_val, nullptr, pv, NHW, DIM, NHW,
        (long long)DIM * NHW, (long long)NHW * DIM);

    // 4) sampling
    sample_kernel<<<NROWS, 256>>>(ctrl, pc_range, pv, po, pa, ps);

    // 5) msda = samp @ W_do + b_do + query
    gemm256<false><<<dim3(2, (NROWS + 127) / 128, 1), 256>>>(
        ps, W_do, b_do, pq, pm, NROWS, DIM, DIM, 0, 0);

    // 6) out = msda @ W_out + b_out
    gemm256<false><<<dim3(2, (NROWS + 127) / 128, 1), 256>>>(
        pm, W_out, b_out, nullptr, out, NROWS, DIM, DIM, 0, 0);
}

// round 2
// speedup vs baseline: 1.9793x; 1.9793x over previous
#include <cuda_runtime.h>
#include <math.h>

#define NB     4
#define NQ     1024
#define DIM    256
#define NHEADS 8
#define NPTS   4
#define GH     200
#define GW     200
#define NHW    (GH*GW)       // 40000
#define NROWS  (NB*NQ)       // 4096

// Scratch (static __device__ arrays: allocation-free per harness rules)
__device__ float g_query[NROWS * DIM];
__device__ float g_off  [NROWS * 64];
__device__ float g_attn [NROWS * 32];
__device__ float g_bevT [(size_t)NB * NHW * DIM];   // ~164 MB, bev transposed to [B, HW, C]
__device__ float g_samp [NROWS * DIM];
__device__ float g_msda [NROWS * DIM];

// ---------------------------------------------------------------------------
// GEMM: C[M x 256] = A @ W + bias (+ res). N fixed at 256. A row-major [M][K].
// 128x128 tile, BK=16, 256 threads, 8x8 per-thread microtile split 2x2
// ---------------------------------------------------------------------------
__global__ __launch_bounds__(256)
void gemm256(const float* __restrict__ A, const float* __restrict__ W,
             const float* __restrict__ bias, const float* __restrict__ res,
             float* __restrict__ C, int M, int K)
{
    __shared__ __align__(16) float As[16][128];
    __shared__ __align__(16) float Bs[16][128];

    const int tid = threadIdx.x;
    const int tx = tid & 15, ty = tid >> 4;
    const int n0 = blockIdx.x * 128;
    const int m0 = blockIdx.y * 128;

    float acc[8][8];
#pragma unroll
    for (int i = 0; i < 8; i++)
#pragma unroll
        for (int j = 0; j < 8; j++) acc[i][j] = 0.f;

    for (int k0 = 0; k0 < K; k0 += 16) {
        {
            // A[m][k] row-major: float4 along k, transpose into As[k][m]
            const int mr = tid >> 2;          // 0..63
            const int kq = (tid & 3) * 4;     // 0,4,8,12
#pragma unroll
            for (int r = 0; r < 2; r++) {
                const int m = mr + 64 * r;
                float4 v;
                if (m0 + m < M) v = *(const float4*)(A + (size_t)(m0 + m) * K + k0 + kq);
                else            v = make_float4(0.f, 0.f, 0.f, 0.f);
                As[kq + 0][m] = v.x; As[kq + 1][m] = v.y;
                As[kq + 2][m] = v.z; As[kq + 3][m] = v.w;
            }
        }
        {
            const int kr = tid >> 4;
            const int nq = (tid & 15) * 8;
            const float* src = W + (size_t)(k0 + kr) * 256 + n0 + nq;
            *(float4*)&Bs[kr][nq]     = *(const float4*)(src);
            *(float4*)&Bs[kr][nq + 4] = *(const float4*)(src + 4);
        }
        __syncthreads();

#pragma unroll
        for (int k = 0; k < 16; k++) {
            float a[8], b[8];
            *(float4*)&a[0] = *(const float4*)&As[k][ty * 4];
            *(float4*)&a[4] = *(const float4*)&As[k][64 + ty * 4];
            *(float4*)&b[0] = *(const float4*)&Bs[k][tx * 4];
            *(float4*)&b[4] = *(const float4*)&Bs[k][64 + tx * 4];
#pragma unroll
            for (int i = 0; i < 8; i++)
#pragma unroll
                for (int j = 0; j < 8; j++)
                    acc[i][j] = fmaf(a[i], b[j], acc[i][j]);
        }
        __syncthreads();
    }

#pragma unroll
    for (int i = 0; i < 8; i++) {
        const int m = m0 + (i < 4 ? ty * 4 + i : 64 + ty * 4 + (i - 4));
        if (m >= M) continue;
#pragma unroll
        for (int j = 0; j < 8; j++) {
            const int n = n0 + (j < 4 ? tx * 4 + j : 64 + tx * 4 + (j - 4));
            float v = acc[i][j] + bias[n];
            if (res) v += res[(size_t)m * 256 + n];
            C[(size_t)m * 256 + n] = v;
        }
    }
}

// ---------------------------------------------------------------------------
// Offsets (64) + attn logits (32) + per-head softmax, one block per query row
// ---------------------------------------------------------------------------
__global__ __launch_bounds__(128)
void offattn_kernel(const float* __restrict__ q,
                    const float* __restrict__ Woff, const float* __restrict__ boff,
                    const float* __restrict__ Wattn, const float* __restrict__ battn,
                    float* __restrict__ off, float* __restrict__ attn)
{
    const int row = blockIdx.x;
    __shared__ float qs[256];
    __shared__ float lg[32];
    const int t = threadIdx.x;
    qs[t]       = q[(size_t)row * 256 + t];
    qs[t + 128] = q[(size_t)row * 256 + 128 + t];
    __syncthreads();

    if (t < 64) {
        float s = boff[t];
#pragma unroll 8
        for (int k = 0; k < 256; k++) s = fmaf(qs[k], Woff[k * 64 + t], s);
        off[(size_t)row * 64 + t] = s;
    } else if (t < 96) {
        const int j = t - 64;
        float s = battn[j];
#pragma unroll 8
        for (int k = 0; k < 256; k++) s = fmaf(qs[k], Wattn[k * 32 + j], s);
        lg[j] = s;
    }
    __syncthreads();

    if (t < 8) {
        float l0 = lg[t*4], l1 = lg[t*4+1], l2 = lg[t*4+2], l3 = lg[t*4+3];
        float m = fmaxf(fmaxf(l0, l1), fmaxf(l2, l3));
        float e0 = expf(l0 - m), e1 = expf(l1 - m), e2 = expf(l2 - m), e3 = expf(l3 - m);
        float inv = 1.f / (e0 + e1 + e2 + e3);
        attn[(size_t)row * 32 + t*4 + 0] = e0 * inv;
        attn[(size_t)row * 32 + t*4 + 1] = e1 * inv;
        attn[(size_t)row * 32 + t*4 + 2] = e2 * inv;
        attn[(size_t)row * 32 + t*4 + 3] = e3 * inv;
    }
}

// ---------------------------------------------------------------------------
// Transpose bev [B, C=256, HW=40000] -> bevT [B, HW, C] (32x32 smem tiles)
// ---------------------------------------------------------------------------
__global__ __launch_bounds__(256)
void transpose_kernel(const float* __restrict__ src, float* __restrict__ dst)
{
    __shared__ float tile[32][33];
    const int b  = blockIdx.z;
    const int p0 = blockIdx.x * 32;   // HW tile (40000 = 1250*32)
    const int c0 = blockIdx.y * 32;   // C tile  (256 = 8*32)

    const float* s = src + ((size_t)b * 256 + c0) * NHW + p0;
#pragma unroll
    for (int i = 0; i < 4; i++) {
        const int c = threadIdx.y + i * 8;
        tile[c][threadIdx.x] = s[(size_t)c * NHW + threadIdx.x];
    }
    __syncthreads();

    float* d = dst + ((size_t)b * NHW + p0) * 256 + c0;
#pragma unroll
    for (int i = 0; i < 4; i++) {
        const int p = threadIdx.y + i * 8;
        d[(size_t)p * 256 + threadIdx.x] = tile[threadIdx.x][p];
    }
}

// ---------------------------------------------------------------------------
// Fused: Bezier ref-center + bilinear gather of RAW bev features (attn/bilinear
// weights folded in) + per-head 256->32 projection with W_val/b_val.
// Mathematically identical to (bev^T @ W_val + b_val) then sample+weight.
// One block per (b,n). Output: msda-input row [256].
// ---------------------------------------------------------------------------
__global__ __launch_bounds__(256)
void fused_sample(const float* __restrict__ ctrl, const float* __restrict__ pcr,
                  const float* __restrict__ bevT,
                  const float* __restrict__ off, const float* __restrict__ attn,
                  const float* __restrict__ W_val, const float* __restrict__ b_val,
                  float* __restrict__ outrow)
{
    const int row = blockIdx.x;      // b*1024 + n
    const int b = row >> 10;
    const int t = threadIdx.x;

    __shared__ int   cidx[32][4];    // (h,p) x corner -> clipped spatial index
    __shared__ float cw  [32][4];    // (h,p) x corner -> weight (bilinear*valid*attn)
    __shared__ float wsum[32];       // per (h,p): sum of 4 corner weights
    __shared__ float g[8][256];      // per head: weighted-sum raw feature vector

    if (t < 32) {
        // Bezier ref center (computed redundantly in 32 threads; cheap)
        const float lox = pcr[0], loy = pcr[1];
        const float spx = pcr[3] - pcr[0], spy = pcr[4] - pcr[1];
        const float* cp = ctrl + (size_t)row * 8;
        const float c0x = cp[0], c0y = cp[1], c1x = cp[2], c1y = cp[3];
        const float c2x = cp[4], c2y = cp[5], c3x = cp[6], c3y = cp[7];
        float sx = 0.f, sy = 0.f;
#pragma unroll
        for (int k = 0; k < 10; k++) {
            const float tt = (float)k / 9.0f;
            const float u = 1.0f - tt;
            const float w0 = u*u*u, w1 = 3.f*u*u*tt, w2 = 3.f*u*tt*tt, w3 = tt*tt*tt;
            const float dx = w0*c0x + w1*c1x + w2*c2x + w3*c3x;
            const float dy = w0*c0y + w1*c1y + w2*c2y + w3*c3y;
            sx += fminf(fmaxf((dx - lox) / spx, 0.01f), 0.99f);
            sy += fminf(fmaxf((dy - loy) / spy, 0.01f), 0.99f);
        }
        const float rcx = sx * 0.1f, rcy = sy * 0.1f;

        const int h = t >> 2, p = t & 3;
        const float ox = off[(size_t)row * 64 + h * 8 + p * 2 + 0];
        const float oy = off[(size_t)row * 64 + h * 8 + p * 2 + 1];
        const float aw = attn[(size_t)row * 32 + h * 4 + p];
        const float x = (rcx + ox / (float)GW) * (float)GW - 0.5f;
        const float y = (rcy + oy / (float)GH) * (float)GH - 0.5f;
        const float fx = floorf(x), fy = floorf(y);
        const int x0 = (int)fx, y0 = (int)fy;
        const int x1 = x0 + 1,  y1 = y0 + 1;
        const float wx = x - fx, wy = y - fy;
        const bool vx0 = (x0 >= 0) & (x0 < GW), vx1 = (x1 >= 0) & (x1 < GW);
        const bool vy0 = (y0 >= 0) & (y0 < GH), vy1 = (y1 >= 0) & (y1 < GH);
        const int cx0 = min(max(x0, 0), GW - 1), cx1 = min(max(x1, 0), GW - 1);
        const int cy0 = min(max(y0, 0), GH - 1), cy1 = min(max(y1, 0), GH - 1);
        const float w00 = (vy0 & vx0) ? (1.f - wx) * (1.f - wy) * aw : 0.f;
        const float w01 = (vy0 & vx1) ? wx * (1.f - wy) * aw : 0.f;
        const float w10 = (vy1 & vx0) ? (1.f - wx) * wy * aw : 0.f;
        const float w11 = (vy1 & vx1) ? wx * wy * aw : 0.f;
        cidx[t][0] = cy0 * GW + cx0;  cw[t][0] = w00;
        cidx[t][1] = cy0 * GW + cx1;  cw[t][1] = w01;
        cidx[t][2] = cy1 * GW + cx0;  cw[t][2] = w10;
        cidx[t][3] = cy1 * GW + cx1;  cw[t][3] = w11;
        wsum[t] = w00 + w01 + w10 + w11;
    }
    __syncthreads();

    // Gather: thread t owns channel c=t; coalesced 128B lines, uniform indices.
    const float* base = bevT + ((size_t)b * NHW) * 256 + t;
    float acc[8];
#pragma unroll
    for (int h = 0; h < 8; h++) acc[h] = 0.f;
#pragma unroll
    for (int hp = 0; hp < 32; hp++) {
        float a = 0.f;
#pragma unroll
        for (int c = 0; c < 4; c++)
            a = fmaf(cw[hp][c], base[(size_t)cidx[hp][c] * 256], a);
        acc[hp >> 2] += a;
    }
#pragma unroll
    for (int h = 0; h < 8; h++) g[h][t] = acc[h];
    __syncthreads();

    // Projection: thread t -> (head h = t>>5, out-dim d = t&31)
    const int h = t >> 5, d = t & 31;
    const float s = wsum[h*4] + wsum[h*4+1] + wsum[h*4+2] + wsum[h*4+3];
    float o = s * b_val[h * 32 + d];
    const float* Wc = W_val + h * 32 + d;
    const float* gh = g[h];
#pragma unroll 8
    for (int c = 0; c < 256; c++)
        o = fmaf(gh[c], Wc[(size_t)c * 256], o);
    outrow[(size_t)row * 256 + h * 32 + d] = o;
}

// ---------------------------------------------------------------------------
extern "C" void kernel_launch(void* const* d_in, const int* in_sizes, int n_in,
                              void* d_out, int out_size)
{
    const float* query_embed = (const float*)d_in[0];
    const float* ctrl        = (const float*)d_in[1];
    const float* bev         = (const float*)d_in[2];
    /* d_in[3] spatial_shapes unused */
    const float* pc_range    = (const float*)d_in[4];
    const float* W_q   = (const float*)d_in[5];
    const float* b_q   = (const float*)d_in[6];
    const float* W_val = (const float*)d_in[7];
    const float* b_val = (const float*)d_in[8];
    const float* W_off = (const float*)d_in[9];
    const float* b_off = (const float*)d_in[10];
    const float* W_attn = (const float*)d_in[11];
    const float* b_attn = (const float*)d_in[12];
    const float* W_do  = (const float*)d_in[13];
    const float* b_do  = (const float*)d_in[14];
    const float* W_out = (const float*)d_in[15];
    const float* b_out = (const float*)d_in[16];
    float* out = (float*)d_out;

    float *pq, *pbT, *po, *pa, *ps, *pm;
    cudaGetSymbolAddress((void**)&pq,  g_query);
    cudaGetSymbolAddress((void**)&pbT, g_bevT);
    cudaGetSymbolAddress((void**)&po,  g_off);
    cudaGetSymbolAddress((void**)&pa,  g_attn);
    cudaGetSymbolAddress((void**)&ps,  g_samp);
    cudaGetSymbolAddress((void**)&pm,  g_msda);

    // 1) query = query_embed @ W_q + b_q
    gemm256<<<dim3(2, (NROWS + 127) / 128), 256>>>(
        query_embed, W_q, b_q, nullptr, pq, NROWS, DIM);

    // 2) offsets / attn / softmax
    offattn_kernel<<<NROWS, 128>>>(pq, W_off, b_off, W_attn, b_attn, po, pa);

    // 3) transpose bev -> bevT [B, HW, C]
    transpose_kernel<<<dim3(NHW / 32, DIM / 32, NB), dim3(32, 8)>>>(bev, pbT);

    // 4) fused sample + per-head value projection (replaces 21 GF value GEMM)
    fused_sample<<<NROWS, 256>>>(ctrl, pc_range, pbT, po, pa, W_val, b_val, ps);

    // 5) msda = samp @ W_do + b_do + query
    gemm256<<<dim3(2, (NROWS + 127) / 128), 256>>>(
        ps, W_do, b_do, pq, pm, NROWS, DIM);

    // 6) out = msda @ W_out + b_out
    gemm256<<<dim3(2, (NROWS + 127) / 128), 256>>>(
        pm, W_out, b_out, nullptr, out, NROWS, DIM);
}